// round 5
// baseline (speedup 1.0000x reference)
#include <cuda_runtime.h>
#include <cuda_bf16.h>
#include <cstdint>

// Problem constants (fixed by the dataset): N=50000 nodes, E=800000 edges,
// IN_FT = OUT_FT = 128. Scratch is static __device__ (no allocations allowed).
#define MAX_N 50176
#define FT    128

__device__ float g_emb[MAX_N * FT];     // aggregated neighbor features
__device__ int   g_rowptr[MAX_N + 1];   // CSR row pointers from sorted edge_dst

// ---------------------------------------------------------------------------
// Kernel 1: build CSR row pointers from the sorted edge_dst array.
// row_ptr[n] = lower_bound(edge_dst, n). (N+1) independent binary searches.
// ---------------------------------------------------------------------------
__global__ void rowptr_kernel(const int* __restrict__ dst, int E, int Nn,
                              int* __restrict__ rp) {
    int n = blockIdx.x * blockDim.x + threadIdx.x;
    if (n > Nn) return;
    int lo = 0, hi = E;
    while (lo < hi) {
        int mid = (lo + hi) >> 1;
        if (dst[mid] < n) lo = mid + 1; else hi = mid;
    }
    rp[n] = lo;
}

// ---------------------------------------------------------------------------
// Kernel 2: weighted neighbor aggregation (CSR SpMM, register accumulation).
// One block (128 threads = 4 warps) per destination node. Each warp owns an
// independent edge stream (e = start+wid, +=4) for memory-level parallelism;
// each lane holds 4 features (float4), so one warp reads a full 512B x-row
// coalesced. 4 warp-partials reduced through shared memory. No atomics.
// ---------------------------------------------------------------------------
__global__ __launch_bounds__(128)
void agg_kernel(const float* __restrict__ x,
                const int* __restrict__ src,
                const float* __restrict__ wgt,
                const int* __restrict__ rp,
                float* __restrict__ emb) {
    int n = blockIdx.x;
    int start = rp[n];
    int end   = rp[n + 1];
    int wid = threadIdx.x >> 5;
    int lid = threadIdx.x & 31;

    float4 acc = make_float4(0.f, 0.f, 0.f, 0.f);
    for (int e = start + wid; e < end; e += 4) {
        int   s = __ldg(&src[e]);
        float w = __ldg(&wgt[e]);
        float4 v = *reinterpret_cast<const float4*>(&x[(size_t)s * FT + lid * 4]);
        acc.x = fmaf(w, v.x, acc.x);
        acc.y = fmaf(w, v.y, acc.y);
        acc.z = fmaf(w, v.z, acc.z);
        acc.w = fmaf(w, v.w, acc.w);
    }

    __shared__ float4 part[4][32];
    part[wid][lid] = acc;
    __syncthreads();

    if (wid == 0) {
        float4 a = part[0][lid];
        float4 b = part[1][lid];
        float4 c = part[2][lid];
        float4 d = part[3][lid];
        float4 s;
        s.x = (a.x + b.x) + (c.x + d.x);
        s.y = (a.y + b.y) + (c.y + d.y);
        s.z = (a.z + b.z) + (c.z + d.z);
        s.w = (a.w + b.w) + (c.w + d.w);
        *reinterpret_cast<float4*>(&emb[(size_t)n * FT + lid * 4]) = s;
    }
}

// ---------------------------------------------------------------------------
// Kernel 3: out = relu([x | emb] @ W + bias), without materializing the concat.
// Tiled SGEMM: M=N_nodes, K=256 (first 128 from x, last 128 from emb), N=128.
// BM=64, BN=128 (full output width), BK=16. 256 threads, each computes a
// 4(row) x 8(col) register tile. All smem compute reads are LDS.128.
// ---------------------------------------------------------------------------
#define BM 64
#define BN 128
#define BK 16
#define TM 4
#define TN 8

__global__ __launch_bounds__(256)
void gemm_kernel(const float* __restrict__ x,
                 const float* __restrict__ emb,
                 const float* __restrict__ W,     // [256, 128] row-major
                 const float* __restrict__ bias,  // [128]
                 float* __restrict__ out,
                 int M) {
    __shared__ float As[BK][BM];   // k-major A tile: 4 KB
    __shared__ float Bs[BK][BN];   // 8 KB

    const int tid = threadIdx.x;
    const int tx = tid & 15;        // 16 col groups of TN=8
    const int ty = tid >> 4;        // 16 row groups of TM=4
    const int block_row = blockIdx.x * BM;

    float acc[TM][TN];
    #pragma unroll
    for (int r = 0; r < TM; r++)
        #pragma unroll
        for (int c = 0; c < TN; c++) acc[r][c] = 0.f;

    // A-load mapping: thread -> (row = tid/4, 4 consecutive k at (tid%4)*4)
    const int a_r  = tid >> 2;
    const int a_kq = (tid & 3) * 4;
    const int a_grow = block_row + a_r;

    for (int k0 = 0; k0 < 2 * FT; k0 += BK) {
        // ---- load A tile (h = [x | emb] virtual concat) ----
        {
            int gk = k0 + a_kq;
            float4 v = make_float4(0.f, 0.f, 0.f, 0.f);
            if (a_grow < M) {
                const float* base = (gk < FT)
                    ? (x   + (size_t)a_grow * FT + gk)
                    : (emb + (size_t)a_grow * FT + (gk - FT));
                v = *reinterpret_cast<const float4*>(base);
            }
            As[a_kq + 0][a_r] = v.x;
            As[a_kq + 1][a_r] = v.y;
            As[a_kq + 2][a_r] = v.z;
            As[a_kq + 3][a_r] = v.w;
        }
        // ---- load B tile: W[k0..k0+16][0..128], 512 float4s, 2 per thread ----
        #pragma unroll
        for (int j = 0; j < 2; j++) {
            int idx = tid + j * 256;          // float4 index in [0,512)
            int k   = idx >> 5;               // [0,16)
            int c4  = (idx & 31) * 4;         // [0,128) step 4
            float4 v = *reinterpret_cast<const float4*>(&W[(size_t)(k0 + k) * BN + c4]);
            *reinterpret_cast<float4*>(&Bs[k][c4]) = v;
        }
        __syncthreads();

        // ---- compute ----
        #pragma unroll
        for (int kk = 0; kk < BK; kk++) {
            float4 av = *reinterpret_cast<const float4*>(&As[kk][ty * TM]);
            float4 b0 = *reinterpret_cast<const float4*>(&Bs[kk][tx * TN]);
            float4 b1 = *reinterpret_cast<const float4*>(&Bs[kk][tx * TN + 4]);
            float a[TM] = {av.x, av.y, av.z, av.w};
            float b[TN] = {b0.x, b0.y, b0.z, b0.w, b1.x, b1.y, b1.z, b1.w};
            #pragma unroll
            for (int r = 0; r < TM; r++)
                #pragma unroll
                for (int c = 0; c < TN; c++)
                    acc[r][c] = fmaf(a[r], b[c], acc[r][c]);
        }
        __syncthreads();
    }

    // ---- epilogue: + bias, relu, store (float4) ----
    float4 bb0 = *reinterpret_cast<const float4*>(&bias[tx * TN]);
    float4 bb1 = *reinterpret_cast<const float4*>(&bias[tx * TN + 4]);
    float bv[TN] = {bb0.x, bb0.y, bb0.z, bb0.w, bb1.x, bb1.y, bb1.z, bb1.w};

    #pragma unroll
    for (int r = 0; r < TM; r++) {
        int grow = block_row + ty * TM + r;
        if (grow >= M) continue;
        float4 o0, o1;
        o0.x = fmaxf(acc[r][0] + bv[0], 0.f);
        o0.y = fmaxf(acc[r][1] + bv[1], 0.f);
        o0.z = fmaxf(acc[r][2] + bv[2], 0.f);
        o0.w = fmaxf(acc[r][3] + bv[3], 0.f);
        o1.x = fmaxf(acc[r][4] + bv[4], 0.f);
        o1.y = fmaxf(acc[r][5] + bv[5], 0.f);
        o1.z = fmaxf(acc[r][6] + bv[6], 0.f);
        o1.w = fmaxf(acc[r][7] + bv[7], 0.f);
        *reinterpret_cast<float4*>(&out[(size_t)grow * BN + tx * TN])     = o0;
        *reinterpret_cast<float4*>(&out[(size_t)grow * BN + tx * TN + 4]) = o1;
    }
}

// ---------------------------------------------------------------------------
// Launch: inputs per metadata order:
//   0: x [N*128] f32, 1: edge_src [E] i32, 2: edge_dst [E] i32,
//   3: edge_weight [E] f32, 4: weight [256*128] f32, 5: bias [128] f32
// ---------------------------------------------------------------------------
extern "C" void kernel_launch(void* const* d_in, const int* in_sizes, int n_in,
                              void* d_out, int out_size) {
    const float* x    = (const float*)d_in[0];
    const int*   esrc = (const int*)d_in[1];
    const int*   edst = (const int*)d_in[2];
    const float* ewgt = (const float*)d_in[3];
    const float* W    = (const float*)d_in[4];
    const float* bias = (const float*)d_in[5];
    float* out = (float*)d_out;

    int Nn = in_sizes[0] / FT;
    int E  = in_sizes[1];

    float* emb;
    int*   rp;
    cudaGetSymbolAddress((void**)&emb, g_emb);
    cudaGetSymbolAddress((void**)&rp,  g_rowptr);

    rowptr_kernel<<<(Nn + 1 + 255) / 256, 256>>>(edst, E, Nn, rp);
    agg_kernel<<<Nn, 128>>>(x, esrc, ewgt, rp, emb);
    gemm_kernel<<<(Nn + BM - 1) / BM, 256>>>(x, emb, W, bias, out, Nn);
}

// round 6
// speedup vs baseline: 1.8522x; 1.8522x over previous
#include <cuda_runtime.h>
#include <cuda_bf16.h>
#include <cstdint>

// Problem constants (fixed by dataset): N=50000, E=800000, IN=OUT=128, fp32.
#define MAX_N 50176
#define FT    128

__device__ float g_emb[MAX_N * FT];     // aggregated neighbor features
__device__ int   g_rowptr[MAX_N + 1];   // CSR row pointers from sorted edge_dst

// ---------------------------------------------------------------------------
// Packed fp32x2 helpers (sm_100+ SIMD fp32 — FFMA2 in SASS, 2x FFMA tput)
// ---------------------------------------------------------------------------
__device__ __forceinline__ unsigned long long fma2(unsigned long long a,
                                                   unsigned long long b,
                                                   unsigned long long c) {
    unsigned long long d;
    asm("fma.rn.f32x2 %0, %1, %2, %3;" : "=l"(d) : "l"(a), "l"(b), "l"(c));
    return d;
}
__device__ __forceinline__ unsigned long long pack2(float lo, float hi) {
    unsigned long long d;
    asm("mov.b64 %0, {%1, %2};" : "=l"(d) : "f"(lo), "f"(hi));
    return d;
}
__device__ __forceinline__ void unpack2(unsigned long long v, float& lo, float& hi) {
    asm("mov.b64 {%0, %1}, %2;" : "=f"(lo), "=f"(hi) : "l"(v));
}

// ---------------------------------------------------------------------------
// Kernel 1: CSR row pointers via linear boundary scan of the SORTED dst array.
// Thread e (1..E-1): fills rp[n] = e for n in (dst[e-1], dst[e]].
// Thread 0: fills [0, dst[0]]. Thread E: fills (dst[E-1], Nn].
// Coalesced 2x read of dst; gaps are tiny for random dst (~avg 1/16 per edge).
// ---------------------------------------------------------------------------
__global__ void rowptr_scan_kernel(const int* __restrict__ dst, int E, int Nn,
                                   int* __restrict__ rp) {
    int e = blockIdx.x * blockDim.x + threadIdx.x;
    if (e > E) return;
    if (e == 0) {
        int d = dst[0];
        for (int n = 0; n <= d; n++) rp[n] = 0;
    } else if (e == E) {
        int d = dst[E - 1];
        for (int n = d + 1; n <= Nn; n++) rp[n] = E;
    } else {
        int d0 = dst[e - 1];
        int d1 = dst[e];
        for (int n = d0 + 1; n <= d1; n++) rp[n] = e;
    }
}

// ---------------------------------------------------------------------------
// Kernel 2: weighted neighbor aggregation — ONE WARP PER NODE.
// Each lane owns 4 features (float4 => 512B/row per warp, coalesced).
// 4-way edge unroll keeps 4 independent row-gathers in flight per warp
// (MLP=4 -> ~8 B/cyc/warp of L2 demand; with 16+ warps/SM we saturate the
// per-SM L2 share). No atomics, no __syncthreads, uniform warp branching.
// ---------------------------------------------------------------------------
__global__ __launch_bounds__(256)
void agg_kernel(const float* __restrict__ x,
                const int* __restrict__ src,
                const float* __restrict__ wgt,
                const int* __restrict__ rp,
                float* __restrict__ emb, int Nn) {
    int gw  = (blockIdx.x * blockDim.x + threadIdx.x) >> 5;   // global warp = node
    if (gw >= Nn) return;
    int lid = threadIdx.x & 31;

    int start = __ldg(&rp[gw]);
    int end   = __ldg(&rp[gw + 1]);

    float4 a0 = make_float4(0.f, 0.f, 0.f, 0.f);
    float4 a1 = a0, a2 = a0, a3 = a0;

    int e = start;
    int e4 = start + ((end - start) & ~3);
    for (; e < e4; e += 4) {
        int   s0 = __ldg(&src[e + 0]), s1 = __ldg(&src[e + 1]);
        int   s2 = __ldg(&src[e + 2]), s3 = __ldg(&src[e + 3]);
        float w0 = __ldg(&wgt[e + 0]), w1 = __ldg(&wgt[e + 1]);
        float w2 = __ldg(&wgt[e + 2]), w3 = __ldg(&wgt[e + 3]);
        float4 v0 = *reinterpret_cast<const float4*>(&x[(size_t)s0 * FT + lid * 4]);
        float4 v1 = *reinterpret_cast<const float4*>(&x[(size_t)s1 * FT + lid * 4]);
        float4 v2 = *reinterpret_cast<const float4*>(&x[(size_t)s2 * FT + lid * 4]);
        float4 v3 = *reinterpret_cast<const float4*>(&x[(size_t)s3 * FT + lid * 4]);
        a0.x = fmaf(w0, v0.x, a0.x); a0.y = fmaf(w0, v0.y, a0.y);
        a0.z = fmaf(w0, v0.z, a0.z); a0.w = fmaf(w0, v0.w, a0.w);
        a1.x = fmaf(w1, v1.x, a1.x); a1.y = fmaf(w1, v1.y, a1.y);
        a1.z = fmaf(w1, v1.z, a1.z); a1.w = fmaf(w1, v1.w, a1.w);
        a2.x = fmaf(w2, v2.x, a2.x); a2.y = fmaf(w2, v2.y, a2.y);
        a2.z = fmaf(w2, v2.z, a2.z); a2.w = fmaf(w2, v2.w, a2.w);
        a3.x = fmaf(w3, v3.x, a3.x); a3.y = fmaf(w3, v3.y, a3.y);
        a3.z = fmaf(w3, v3.z, a3.z); a3.w = fmaf(w3, v3.w, a3.w);
    }
    for (; e < end; e++) {
        int   s = __ldg(&src[e]);
        float w = __ldg(&wgt[e]);
        float4 v = *reinterpret_cast<const float4*>(&x[(size_t)s * FT + lid * 4]);
        a0.x = fmaf(w, v.x, a0.x); a0.y = fmaf(w, v.y, a0.y);
        a0.z = fmaf(w, v.z, a0.z); a0.w = fmaf(w, v.w, a0.w);
    }

    float4 s;
    s.x = (a0.x + a1.x) + (a2.x + a3.x);
    s.y = (a0.y + a1.y) + (a2.y + a3.y);
    s.z = (a0.z + a1.z) + (a2.z + a3.z);
    s.w = (a0.w + a1.w) + (a2.w + a3.w);
    *reinterpret_cast<float4*>(&emb[(size_t)gw * FT + lid * 4]) = s;
}

// ---------------------------------------------------------------------------
// Kernel 3: out = relu([x | emb] @ W + bias), concat never materialized.
// BM=64, BN=128, BK=16, 256 threads, 4x8 per-thread tile — but the inner
// product now runs on PACKED fp32x2 (FFMA2): acc pairs along N, B pairs come
// directly out of LDS.128, A is broadcast-packed once per row per kk.
// Doubles the fp32 pipe throughput vs scalar FFMA.
// ---------------------------------------------------------------------------
#define BM 64
#define BN 128
#define BK 16
#define TM 4
#define TN 8

__global__ __launch_bounds__(256)
void gemm_kernel(const float* __restrict__ x,
                 const float* __restrict__ emb,
                 const float* __restrict__ W,     // [256, 128] row-major
                 const float* __restrict__ bias,  // [128]
                 float* __restrict__ out,
                 int M) {
    __shared__ __align__(16) float As[BK][BM];   // 4 KB
    __shared__ __align__(16) float Bs[BK][BN];   // 8 KB

    const int tid = threadIdx.x;
    const int tx = tid & 15;        // 16 col groups of TN=8
    const int ty = tid >> 4;        // 16 row groups of TM=4
    const int block_row = blockIdx.x * BM;

    unsigned long long acc[TM][TN / 2];   // packed pairs
    const unsigned long long zz = 0ull;   // {0.f, 0.f}
    #pragma unroll
    for (int r = 0; r < TM; r++)
        #pragma unroll
        for (int j = 0; j < TN / 2; j++) acc[r][j] = zz;

    const int a_r  = tid >> 2;
    const int a_kq = (tid & 3) * 4;
    const int a_grow = block_row + a_r;

    for (int k0 = 0; k0 < 2 * FT; k0 += BK) {
        // ---- load A tile (virtual concat [x | emb]) ----
        {
            int gk = k0 + a_kq;
            float4 v = make_float4(0.f, 0.f, 0.f, 0.f);
            if (a_grow < M) {
                const float* base = (gk < FT)
                    ? (x   + (size_t)a_grow * FT + gk)
                    : (emb + (size_t)a_grow * FT + (gk - FT));
                v = *reinterpret_cast<const float4*>(base);
            }
            As[a_kq + 0][a_r] = v.x;
            As[a_kq + 1][a_r] = v.y;
            As[a_kq + 2][a_r] = v.z;
            As[a_kq + 3][a_r] = v.w;
        }
        // ---- load B tile: 512 float4s, 2 per thread ----
        #pragma unroll
        for (int j = 0; j < 2; j++) {
            int idx = tid + j * 256;
            int k   = idx >> 5;
            int c4  = (idx & 31) * 4;
            float4 v = *reinterpret_cast<const float4*>(&W[(size_t)(k0 + k) * BN + c4]);
            *reinterpret_cast<float4*>(&Bs[k][c4]) = v;
        }
        __syncthreads();

        // ---- compute: packed fp32x2 outer product ----
        #pragma unroll
        for (int kk = 0; kk < BK; kk++) {
            float4 av = *reinterpret_cast<const float4*>(&As[kk][ty * TM]);
            // B pairs straight from LDS.128 (adjacent floats = packed f32x2)
            ulonglong2 bp0 = *reinterpret_cast<const ulonglong2*>(&Bs[kk][tx * TN]);
            ulonglong2 bp1 = *reinterpret_cast<const ulonglong2*>(&Bs[kk][tx * TN + 4]);
            unsigned long long b[4] = {bp0.x, bp0.y, bp1.x, bp1.y};
            unsigned long long pa[TM];
            pa[0] = pack2(av.x, av.x);
            pa[1] = pack2(av.y, av.y);
            pa[2] = pack2(av.z, av.z);
            pa[3] = pack2(av.w, av.w);
            #pragma unroll
            for (int r = 0; r < TM; r++)
                #pragma unroll
                for (int j = 0; j < 4; j++)
                    acc[r][j] = fma2(pa[r], b[j], acc[r][j]);
        }
        __syncthreads();
    }

    // ---- epilogue: + bias, relu, float4 stores ----
    float4 bb0 = *reinterpret_cast<const float4*>(&bias[tx * TN]);
    float4 bb1 = *reinterpret_cast<const float4*>(&bias[tx * TN + 4]);
    float bv[TN] = {bb0.x, bb0.y, bb0.z, bb0.w, bb1.x, bb1.y, bb1.z, bb1.w};

    #pragma unroll
    for (int r = 0; r < TM; r++) {
        int grow = block_row + ty * TM + r;
        if (grow >= M) continue;
        float c[TN];
        #pragma unroll
        for (int j = 0; j < TN / 2; j++)
            unpack2(acc[r][j], c[2 * j], c[2 * j + 1]);
        float4 o0, o1;
        o0.x = fmaxf(c[0] + bv[0], 0.f);
        o0.y = fmaxf(c[1] + bv[1], 0.f);
        o0.z = fmaxf(c[2] + bv[2], 0.f);
        o0.w = fmaxf(c[3] + bv[3], 0.f);
        o1.x = fmaxf(c[4] + bv[4], 0.f);
        o1.y = fmaxf(c[5] + bv[5], 0.f);
        o1.z = fmaxf(c[6] + bv[6], 0.f);
        o1.w = fmaxf(c[7] + bv[7], 0.f);
        *reinterpret_cast<float4*>(&out[(size_t)grow * BN + tx * TN])     = o0;
        *reinterpret_cast<float4*>(&out[(size_t)grow * BN + tx * TN + 4]) = o1;
    }
}

// ---------------------------------------------------------------------------
// Launch. Inputs (metadata order):
//   0: x [N*128] f32, 1: edge_src [E] i32, 2: edge_dst [E] i32 (sorted),
//   3: edge_weight [E] f32, 4: weight [256*128] f32, 5: bias [128] f32
// ---------------------------------------------------------------------------
extern "C" void kernel_launch(void* const* d_in, const int* in_sizes, int n_in,
                              void* d_out, int out_size) {
    const float* x    = (const float*)d_in[0];
    const int*   esrc = (const int*)d_in[1];
    const int*   edst = (const int*)d_in[2];
    const float* ewgt = (const float*)d_in[3];
    const float* W    = (const float*)d_in[4];
    const float* bias = (const float*)d_in[5];
    float* out = (float*)d_out;

    int Nn = in_sizes[0] / FT;
    int E  = in_sizes[1];

    float* emb;
    int*   rp;
    cudaGetSymbolAddress((void**)&emb, g_emb);
    cudaGetSymbolAddress((void**)&rp,  g_rowptr);

    rowptr_scan_kernel<<<(E + 1 + 255) / 256, 256>>>(edst, E, Nn, rp);
    agg_kernel<<<(Nn * 32 + 255) / 256, 256>>>(x, esrc, ewgt, rp, emb, Nn);
    gemm_kernel<<<(Nn + BM - 1) / BM, 256>>>(x, emb, W, bias, out, Nn);
}